// round 10
// baseline (speedup 1.0000x reference)
#include <cuda_runtime.h>
#include <cuda_fp16.h>
#include <cstdint>
#include <math.h>

#define S_LEN 2048
#define HID   5120
#define NH    40
#define HD    128
#define QKV_N (3*HID)   // 15360

// ---- fp16 mma GEMM tiling (swizzled smem, no padding) ----
#define MT 128
#define NT 128
#define KT 32
#define TILE_BYTES (128*64)             // 8192: 128 rows x 64B (32 halves), XOR-swizzled
#define STAGE_SPLIT  (3*TILE_BYTES)     // A + Bhi + Blo = 24576
#define STAGE_SINGLE (2*TILE_BYTES)     // A + B        = 16384
#define STAGES_SPLIT  4
#define STAGES_SINGLE 4
#define GEMM_SMEM_SPLIT  (STAGES_SPLIT*STAGE_SPLIT)     // 98304  (x2 CTA = 196608)
#define GEMM_SMEM_SINGLE (STAGES_SINGLE*STAGE_SINGLE)   // 65536

// smem swizzle: row r (64B rows), 16B chunk c -> byte offset
//   off = r*64 + ((c ^ ((r>>1)&3)) << 4)
// conflict-free for STS phases and 8-row ldmatrix wavefronts; 16B aligned.

// ---- flash-attention (fp16 tensor, BQ=128, triple-buffered K/V) ----
#define BQ 128
#define BKV 64
#define AQS 136                          // halves stride for 128-wide rows
#define KV_TILE (BKV*AQS*2)              // 17408
#define Q_TILE  (BQ*AQS*2)               // 34816
#define KVBUF   (3*KV_TILE)              // Kh,Kl,Vh = 52224
#define KV_STAGES 3
#define FSMEM   (2*Q_TILE + KV_STAGES*KVBUF)   // 226304

// Scratch (allocation-free rule: __device__ globals)
__device__ __half g_qkvh[(size_t)S_LEN * QKV_N];       // QKV hi fp16
__device__ __half g_qkvl[(size_t)S_LEN * QKV_N];       // QKV lo fp16 (Q,K only)
__device__ __half g_h16[(size_t)S_LEN * HID];          // hidden fp16
__device__ __half g_wp_hi[(size_t)QKV_N * HID];        // Wpack hi (V rows plain)
__device__ __half g_wp_lo[(size_t)QKV_N * HID];        // Wpack lo (Q,K rows)
__device__ __half g_wo16[(size_t)HID * HID];           // Wo fp16
__device__ __half g_attno16[(size_t)S_LEN * HID];      // attention out fp16

// ============================================================================
// PTX helpers
// ============================================================================
__device__ __forceinline__ uint32_t smem_u32(const void* p) {
    uint32_t a;
    asm("{ .reg .u64 t; cvta.to.shared.u64 t, %1; cvt.u32.u64 %0, t; }"
        : "=r"(a) : "l"(p));
    return a;
}

__device__ __forceinline__ void ldsm4(uint32_t* r, uint32_t a) {
    asm volatile("ldmatrix.sync.aligned.m8n8.x4.shared.b16 {%0,%1,%2,%3}, [%4];"
                 : "=r"(r[0]), "=r"(r[1]), "=r"(r[2]), "=r"(r[3]) : "r"(a));
}
__device__ __forceinline__ void ldsm4t(uint32_t* r, uint32_t a) {
    asm volatile("ldmatrix.sync.aligned.m8n8.x4.trans.shared.b16 {%0,%1,%2,%3}, [%4];"
                 : "=r"(r[0]), "=r"(r[1]), "=r"(r[2]), "=r"(r[3]) : "r"(a));
}

__device__ __forceinline__ void mma16(float* c, const uint32_t* a,
                                      uint32_t b0, uint32_t b1) {
    asm volatile(
        "mma.sync.aligned.m16n8k16.row.col.f32.f16.f16.f32 "
        "{%0,%1,%2,%3}, {%4,%5,%6,%7}, {%8,%9}, {%0,%1,%2,%3};"
        : "+f"(c[0]), "+f"(c[1]), "+f"(c[2]), "+f"(c[3])
        : "r"(a[0]), "r"(a[1]), "r"(a[2]), "r"(a[3]), "r"(b0), "r"(b1));
}

__device__ __forceinline__ uint32_t packh2(float a, float b) {
    __half2 h = __floats2half2_rn(a, b);
    return *reinterpret_cast<uint32_t*>(&h);
}

__device__ __forceinline__ void split4(const float4 v, uint2& hi, uint2& lo) {
    __half h0 = __float2half_rn(v.x), h1 = __float2half_rn(v.y);
    __half h2 = __float2half_rn(v.z), h3 = __float2half_rn(v.w);
    hi.x = packh2(v.x, v.y);
    hi.y = packh2(v.z, v.w);
    lo.x = packh2(v.x - __half2float(h0), v.y - __half2float(h1));
    lo.y = packh2(v.z - __half2float(h2), v.w - __half2float(h3));
}
__device__ __forceinline__ uint2 cvt4(const float4 v) {
    uint2 r; r.x = packh2(v.x, v.y); r.y = packh2(v.z, v.w); return r;
}

__device__ __forceinline__ void cpa16(uint32_t dst, const void* src) {
    asm volatile("cp.async.cg.shared.global [%0], [%1], 16;"
                 :: "r"(dst), "l"(src) : "memory");
}
__device__ __forceinline__ void cp_commit() {
    asm volatile("cp.async.commit_group;" ::: "memory");
}
template<int N> __device__ __forceinline__ void cp_wait() {
    asm volatile("cp.async.wait_group %0;" :: "n"(N) : "memory");
}

// ============================================================================
// Pre-conversion kernels
// ============================================================================
__global__ void cvt_split_kernel(const float4* __restrict__ in,
                                 uint2* __restrict__ hi, uint2* __restrict__ lo,
                                 int n4) {
    for (int i = blockIdx.x * blockDim.x + threadIdx.x; i < n4;
         i += gridDim.x * blockDim.x) {
        uint2 h, l; split4(in[i], h, l);
        hi[i] = h; lo[i] = l;
    }
}
// fused plain conversions: hidden, Wpack V rows, Wo
__global__ void cvt_fused3_kernel(const float4* __restrict__ a, uint2* __restrict__ ao, int na,
                                  const float4* __restrict__ b, uint2* __restrict__ bo, int nb,
                                  const float4* __restrict__ c, uint2* __restrict__ co, int nc) {
    const int tot = na + nb + nc;
    for (int i = blockIdx.x * blockDim.x + threadIdx.x; i < tot;
         i += gridDim.x * blockDim.x) {
        if (i < na) ao[i] = cvt4(a[i]);
        else if (i < na + nb) bo[i - na] = cvt4(b[i - na]);
        else co[i - na - nb] = cvt4(c[i - na - nb]);
    }
}

// ============================================================================
// fp16 tensor GEMM (TN), cp.async pipeline (issue AFTER compute, R7 order),
// XOR-swizzled smem (no padding) -> 4 stages fit at 2 CTAs/SM.
// SPLITB: B = Bh + Bl for tiles with n0 < 2*HID (Q,K); V tiles plain fp16.
// SPLITOUT: write hi/lo fp16 split of the fp32 accumulator (lo for Q,K only).
// ============================================================================
template<bool SPLITB, bool SPLITOUT>
__global__ __launch_bounds__(256, 2)
void gemm16p(const __half* __restrict__ A, const __half* __restrict__ Bh,
             const __half* __restrict__ Bl, float* __restrict__ Cf,
             __half* __restrict__ Chi, __half* __restrict__ Clo,
             int M, int N, int K) {
    extern __shared__ __align__(16) char sm[];
    const uint32_t sb = smem_u32(sm);
    constexpr uint32_t stageBytes = SPLITB ? STAGE_SPLIT : STAGE_SINGLE;
    constexpr int STAGES = SPLITB ? STAGES_SPLIT : STAGES_SINGLE;

    const int t   = threadIdx.x;
    const int wid = t >> 5;
    const int ln  = t & 31;
    const int m0  = blockIdx.x * MT;
    const int n0  = blockIdx.y * NT;
    const int wm  = (wid >> 1) * 32;
    const int wn  = (wid & 1) * 64;
    const bool useBl = SPLITB && (n0 < 2 * HID);   // Q,K tiles only

    // cp.async geometry: rows r0, r0+64; chunk sg (16B). Swizzled dst.
    const int r0 = t >> 2;             // 0..63
    const int sg = t & 3;              // 0..3
    const __half* Ag0 = A  + (size_t)(m0 + r0) * K + sg * 8;
    const __half* Ag1 = Ag0 + (size_t)64 * K;
    const __half* Bh0 = Bh + (size_t)(n0 + r0) * K + sg * 8;
    const __half* Bh1 = Bh0 + (size_t)64 * K;
    const __half* Bl0 = SPLITB ? (Bl + (size_t)(n0 + r0) * K + sg * 8) : (const __half*)0;
    const __half* Bl1 = SPLITB ? (Bl0 + (size_t)64 * K) : (const __half*)0;
    const uint32_t d0 = (uint32_t)r0 * 64 + (uint32_t)((sg ^ ((r0 >> 1) & 3)) << 4);
    const uint32_t d1 = d0 + 64 * 64;  // row+64: (r>>1)&3 unchanged (+32 ≡ 0 mod 4)

    // ldmatrix lane geometry (swizzle applied per-ks in loop)
    const int rowA = wm + (ln & 15);
    const uint32_t aBase = (uint32_t)rowA * 64;
    const uint32_t aSw   = (uint32_t)((rowA >> 1) & 3);
    const uint32_t aHi   = (uint32_t)(ln >> 4);          // chunk parity
    const int rowB = wn + (ln & 7) + 8 * (ln >> 4);
    const uint32_t bBase = (uint32_t)rowB * 64;
    const uint32_t bSw   = (uint32_t)((rowB >> 1) & 3);
    const uint32_t bHi   = (uint32_t)((ln >> 3) & 1);

    float acc[2][8][4];
#pragma unroll
    for (int mi = 0; mi < 2; mi++)
#pragma unroll
        for (int nf = 0; nf < 8; nf++)
#pragma unroll
            for (int r = 0; r < 4; r++) acc[mi][nf][r] = 0.0f;

    const int NKT = K / KT;   // 160

    auto issue = [&](int st, int kt) {
        const uint32_t base = sb + (uint32_t)st * stageBytes;
        const size_t ko = (size_t)kt * KT;
        cpa16(base + d0, Ag0 + ko);
        cpa16(base + d1, Ag1 + ko);
        cpa16(base + TILE_BYTES + d0, Bh0 + ko);
        cpa16(base + TILE_BYTES + d1, Bh1 + ko);
        if (useBl) {
            cpa16(base + 2 * TILE_BYTES + d0, Bl0 + ko);
            cpa16(base + 2 * TILE_BYTES + d1, Bl1 + ko);
        }
    };

#pragma unroll
    for (int s = 0; s < STAGES - 1; s++) { issue(s, s); cp_commit(); }

#pragma unroll 1
    for (int kt = 0; kt < NKT; kt++) {
        cp_wait<STAGES - 2>();
        __syncthreads();

        const uint32_t so = sb + (uint32_t)(kt % STAGES) * stageBytes;
#pragma unroll
        for (int ks = 0; ks < 2; ks++) {
            const uint32_t ca = ((2u * ks + aHi) ^ aSw) << 4;
            const uint32_t cb = ((2u * ks + bHi) ^ bSw) << 4;
            uint32_t af[2][4];
            ldsm4(af[0], so + aBase + ca);
            ldsm4(af[1], so + aBase + 16 * 64 + ca);   // row+16: swizzle unchanged
            uint32_t bh[4][4];
#pragma unroll
            for (int p = 0; p < 4; p++)
                ldsm4(bh[p], so + TILE_BYTES + bBase + (uint32_t)p * (16 * 64) + cb);
            uint32_t bl[4][4];
            if (useBl) {
#pragma unroll
                for (int p = 0; p < 4; p++)
                    ldsm4(bl[p], so + 2 * TILE_BYTES + bBase + (uint32_t)p * (16 * 64) + cb);
            }
#pragma unroll
            for (int mi = 0; mi < 2; mi++)
#pragma unroll
                for (int nf = 0; nf < 8; nf++) {
                    mma16(acc[mi][nf], af[mi],
                          bh[nf >> 1][(nf & 1) * 2], bh[nf >> 1][(nf & 1) * 2 + 1]);
                    if (useBl)
                        mma16(acc[mi][nf], af[mi],
                              bl[nf >> 1][(nf & 1) * 2], bl[nf >> 1][(nf & 1) * 2 + 1]);
                }
        }

        const int nk = kt + STAGES - 1;
        if (nk < NKT) issue(nk % STAGES, nk);
        cp_commit();
    }

    // epilogue
    const bool writeLo = SPLITOUT && (n0 < 2 * HID);
#pragma unroll
    for (int mi = 0; mi < 2; mi++) {
        const int r = m0 + wm + mi * 16 + (ln >> 2);
#pragma unroll
        for (int nf = 0; nf < 8; nf++) {
            const int cc = n0 + wn + nf * 8 + (ln & 3) * 2;
            if (SPLITOUT) {
#pragma unroll
                for (int hh = 0; hh < 2; hh++) {
                    const float v0 = acc[mi][nf][2 * hh], v1 = acc[mi][nf][2 * hh + 1];
                    const __half h0 = __float2half_rn(v0), h1 = __float2half_rn(v1);
                    const size_t off = (size_t)(r + 8 * hh) * N + cc;
                    *(uint32_t*)(Chi + off) = packh2(v0, v1);
                    if (writeLo)
                        *(uint32_t*)(Clo + off) =
                            packh2(v0 - __half2float(h0), v1 - __half2float(h1));
                }
            } else {
                *(float2*)(Cf + (size_t)r * N + cc) =
                    make_float2(acc[mi][nf][0], acc[mi][nf][1]);
                *(float2*)(Cf + (size_t)(r + 8) * N + cc) =
                    make_float2(acc[mi][nf][2], acc[mi][nf][3]);
            }
        }
    }
}

// ============================================================================
// Flash attention (unchanged from R9), fp16 tensor, causal. BQ=128, 256 thr,
// triple-buffered K/V via cp.async; one sync per KV block; Q in registers.
// S = QhKh + QhKl + QlKh; O += P*Vh. Grid (NH, S/BQ) with qb reversed.
// ============================================================================
__global__ __launch_bounds__(256, 1)
void flash16_kernel(const __half* __restrict__ qh, const __half* __restrict__ ql,
                    __half* __restrict__ out) {
    extern __shared__ __align__(16) char sm[];
    const uint32_t sb = smem_u32(sm);
    const uint32_t uQh = sb;
    const uint32_t uQl = sb + Q_TILE;
    const uint32_t uBuf0 = sb + 2 * Q_TILE;

    const int head = blockIdx.x;
    const int qb   = (int)gridDim.y - 1 - (int)blockIdx.y;   // heavy first
    const int q0   = qb * BQ;
    const int t    = threadIdx.x;
    const int w    = t >> 5;
    const int ln   = t & 31;
    const int m0w  = w * 16;
    const float scale = 0.08838834764831845f;   // 1/sqrt(128)

    const int lr  = t >> 2;            // 0..63
    const int lc  = (t & 3) * 4;       // chunk base 0,4,8,12

    auto issueKV = [&](int kb) {
        const uint32_t base = uBuf0 + (uint32_t)(kb % KV_STAGES) * KVBUF;
        const size_t gk = (size_t)(kb * BKV + lr) * QKV_N + HID + head * HD;
        const size_t gv = gk + HID;
        const uint32_t ro = (uint32_t)lr * (AQS * 2);
#pragma unroll
        for (int i = 0; i < 4; i++) {
            const int c = lc + i;
            cpa16(base + ro + c * 16, qh + gk + c * 8);                    // Kh
            cpa16(base + KV_TILE + ro + c * 16, ql + gk + c * 8);          // Kl
            cpa16(base + 2 * KV_TILE + ro + c * 16, qh + gv + c * 8);      // Vh
        }
    };

    // ---- prologue: Q + KV0 as one group, KV1 as second ----
#pragma unroll
    for (int pass = 0; pass < 2; pass++) {
        const int r = pass * 64 + lr;
        const size_t go = (size_t)(q0 + r) * QKV_N + head * HD;
        const uint32_t ro = (uint32_t)r * (AQS * 2);
#pragma unroll
        for (int i = 0; i < 4; i++) {
            const int c = lc + i;
            cpa16(uQh + ro + c * 16, qh + go + c * 8);
            cpa16(uQl + ro + c * 16, ql + go + c * 8);
        }
    }
    issueKV(0);
    cp_commit();          // group: Q + KV0
    issueKV(1);
    cp_commit();          // group: KV1

    const int nkb = 2 * (qb + 1);

    cp_wait<1>();         // Q + KV0 ready
    __syncthreads();

    // ---- hoist Q fragments (hi/lo) to registers ----
    const uint32_t aQ = ((uint32_t)(m0w + (ln & 15)) * AQS + 8u * (ln >> 4)) * 2;
    uint32_t qhf[8][4], qlf[8][4];
#pragma unroll
    for (int ks = 0; ks < 8; ks++) {
        ldsm4(qhf[ks], uQh + aQ + ks * 32);
        ldsm4(qlf[ks], uQl + aQ + ks * 32);
    }

    float m_i[2] = {-1e30f, -1e30f};
    float l_i[2] = {0.0f, 0.0f};
    float o[16][4];
#pragma unroll
    for (int d = 0; d < 16; d++)
#pragma unroll
        for (int r = 0; r < 4; r++) o[d][r] = 0.0f;

    const uint32_t bK = ((uint32_t)((ln & 7) + 8 * (ln >> 4)) * AQS + 8u * ((ln >> 3) & 1)) * 2;
    const uint32_t bV = ((uint32_t)((ln & 7) + 8 * ((ln >> 3) & 1)) * AQS + 8u * (ln >> 4)) * 2;

    const int r1g = q0 + m0w + (ln >> 2);
    const int r2g = r1g + 8;

#pragma unroll 1
    for (int kb = 0; kb < nkb; kb++) {
        const int k0 = kb * BKV;

        if (kb + 2 < nkb) issueKV(kb + 2);
        cp_commit();

        if (k0 <= q0 + m0w + 15) {
            const uint32_t cKh = uBuf0 + (uint32_t)(kb % KV_STAGES) * KVBUF;
            const uint32_t cKl = cKh + KV_TILE;
            const uint32_t cVh = cKh + 2 * KV_TILE;

            float s[8][4];
#pragma unroll
            for (int nf = 0; nf < 8; nf++)
#pragma unroll
                for (int r = 0; r < 4; r++) s[nf][r] = 0.0f;

#pragma unroll
            for (int ks = 0; ks < 8; ks++) {
                const uint32_t ko = ks * 32;
                uint32_t kh[4][4], kl[4][4];
#pragma unroll
                for (int p = 0; p < 4; p++) {
                    ldsm4(kh[p], cKh + bK + p * (16 * AQS * 2) + ko);
                    ldsm4(kl[p], cKl + bK + p * (16 * AQS * 2) + ko);
                }
#pragma unroll
                for (int nf = 0; nf < 8; nf++) {
                    const uint32_t h0 = kh[nf >> 1][(nf & 1) * 2];
                    const uint32_t h1 = kh[nf >> 1][(nf & 1) * 2 + 1];
                    const uint32_t l0 = kl[nf >> 1][(nf & 1) * 2];
                    const uint32_t l1 = kl[nf >> 1][(nf & 1) * 2 + 1];
                    mma16(s[nf], qhf[ks], h0, h1);
                    mma16(s[nf], qhf[ks], l0, l1);
                    mma16(s[nf], qlf[ks], h0, h1);
                }
            }

            const bool needMask = (k0 + BKV - 1 > q0 + m0w);
            float mx1 = -1e30f, mx2 = -1e30f;
#pragma unroll
            for (int nf = 0; nf < 8; nf++) {
                float v0 = s[nf][0] * scale, v1 = s[nf][1] * scale;
                float v2 = s[nf][2] * scale, v3 = s[nf][3] * scale;
                if (needMask) {
                    const int cb = k0 + nf * 8 + 2 * (ln & 3);
                    if (cb     > r1g) v0 = -1e30f;
                    if (cb + 1 > r1g) v1 = -1e30f;
                    if (cb     > r2g) v2 = -1e30f;
                    if (cb + 1 > r2g) v3 = -1e30f;
                }
                s[nf][0] = v0; s[nf][1] = v1; s[nf][2] = v2; s[nf][3] = v3;
                mx1 = fmaxf(mx1, fmaxf(v0, v1));
                mx2 = fmaxf(mx2, fmaxf(v2, v3));
            }
            mx1 = fmaxf(mx1, __shfl_xor_sync(0xffffffffu, mx1, 1));
            mx1 = fmaxf(mx1, __shfl_xor_sync(0xffffffffu, mx1, 2));
            mx2 = fmaxf(mx2, __shfl_xor_sync(0xffffffffu, mx2, 1));
            mx2 = fmaxf(mx2, __shfl_xor_sync(0xffffffffu, mx2, 2));

            const float mn1 = fmaxf(m_i[0], mx1);
            const float mn2 = fmaxf(m_i[1], mx2);
            const float corr1 = __expf(m_i[0] - mn1);
            const float corr2 = __expf(m_i[1] - mn2);
            m_i[0] = mn1; m_i[1] = mn2;

            float rs1 = 0.0f, rs2 = 0.0f;
#pragma unroll
            for (int nf = 0; nf < 8; nf++) {
                float p0 = __expf(s[nf][0] - mn1);
                float p1 = __expf(s[nf][1] - mn1);
                float p2 = __expf(s[nf][2] - mn2);
                float p3 = __expf(s[nf][3] - mn2);
                rs1 += p0 + p1; rs2 += p2 + p3;
                s[nf][0] = p0; s[nf][1] = p1; s[nf][2] = p2; s[nf][3] = p3;
            }
            rs1 += __shfl_xor_sync(0xffffffffu, rs1, 1);
            rs1 += __shfl_xor_sync(0xffffffffu, rs1, 2);
            rs2 += __shfl_xor_sync(0xffffffffu, rs2, 1);
            rs2 += __shfl_xor_sync(0xffffffffu, rs2, 2);
            l_i[0] = l_i[0] * corr1 + rs1;
            l_i[1] = l_i[1] * corr2 + rs2;

#pragma unroll
            for (int d = 0; d < 16; d++) {
                o[d][0] *= corr1; o[d][1] *= corr1;
                o[d][2] *= corr2; o[d][3] *= corr2;
            }

            uint32_t pa[4][4];
#pragma unroll
            for (int tk = 0; tk < 4; tk++) {
                pa[tk][0] = packh2(s[2 * tk][0],     s[2 * tk][1]);
                pa[tk][1] = packh2(s[2 * tk][2],     s[2 * tk][3]);
                pa[tk][2] = packh2(s[2 * tk + 1][0], s[2 * tk + 1][1]);
                pa[tk][3] = packh2(s[2 * tk + 1][2], s[2 * tk + 1][3]);
            }

#pragma unroll
            for (int tk = 0; tk < 4; tk++) {
                const uint32_t rowo = (uint32_t)(16 * tk) * AQS * 2;
#pragma unroll
                for (int p = 0; p < 8; p++) {
                    uint32_t vh[4];
                    ldsm4t(vh, cVh + rowo + bV + (uint32_t)p * 32);
                    mma16(o[2 * p],     pa[tk], vh[0], vh[1]);
                    mma16(o[2 * p + 1], pa[tk], vh[2], vh[3]);
                }
            }
        }

        if (kb + 1 < nkb) {
            cp_wait<1>();      // next block's K/V landed
            __syncthreads();   // single barrier per iteration
        }
    }

    // ---- epilogue: fp16 output ----
    const float inv1 = 1.0f / l_i[0];
    const float inv2 = 1.0f / l_i[1];
#pragma unroll
    for (int d = 0; d < 16; d++) {
        const int cc = head * HD + d * 8 + 2 * (ln & 3);
        *(__half2*)(out + (size_t)r1g * HID + cc) =
            __floats2half2_rn(o[d][0] * inv1, o[d][1] * inv1);
        *(__half2*)(out + (size_t)r2g * HID + cc) =
            __floats2half2_rn(o[d][2] * inv2, o[d][3] * inv2);
    }
}

// ============================================================================
// Launch
// ============================================================================
extern "C" void kernel_launch(void* const* d_in, const int* in_sizes, int n_in,
                              void* d_out, int out_size) {
    const float* hidden = (const float*)d_in[0];
    const float* wpack  = (const float*)d_in[1];
    const float* wo     = (const float*)d_in[2];
    float* out = (float*)d_out;

    __half *qkvh, *qkvl, *h16, *wph, *wpl, *wo16, *at16;
    cudaGetSymbolAddress((void**)&qkvh, g_qkvh);
    cudaGetSymbolAddress((void**)&qkvl, g_qkvl);
    cudaGetSymbolAddress((void**)&h16,  g_h16);
    cudaGetSymbolAddress((void**)&wph,  g_wp_hi);
    cudaGetSymbolAddress((void**)&wpl,  g_wp_lo);
    cudaGetSymbolAddress((void**)&wo16, g_wo16);
    cudaGetSymbolAddress((void**)&at16, g_attno16);

    cudaFuncSetAttribute((const void*)gemm16p<true, true>,
                         cudaFuncAttributeMaxDynamicSharedMemorySize, GEMM_SMEM_SPLIT);
    cudaFuncSetAttribute((const void*)gemm16p<false, false>,
                         cudaFuncAttributeMaxDynamicSharedMemorySize, GEMM_SMEM_SINGLE);
    cudaFuncSetAttribute((const void*)flash16_kernel,
                         cudaFuncAttributeMaxDynamicSharedMemorySize, FSMEM);

    // 0. pre-conversions
    const size_t qkRows = (size_t)2 * HID * HID;   // first 10240 rows of Wpack
    cvt_split_kernel<<<8192, 256>>>((const float4*)wpack, (uint2*)wph, (uint2*)wpl,
                                    (int)(qkRows / 4));
    cvt_fused3_kernel<<<8192, 256>>>(
        (const float4*)hidden, (uint2*)h16, (int)((size_t)S_LEN * HID / 4),
        (const float4*)(wpack + qkRows), (uint2*)(wph + qkRows),
        (int)((size_t)HID * HID / 4),
        (const float4*)wo, (uint2*)wo16, (int)((size_t)HID * HID / 4));

    // 1. QKV projection (split-B for Q,K tiles; split-out hi/lo)
    dim3 g1(S_LEN / MT, QKV_N / NT);
    gemm16p<true, true><<<g1, 256, GEMM_SMEM_SPLIT>>>(
        h16, wph, wpl, nullptr, qkvh, qkvl, S_LEN, QKV_N, HID);

    // 2. Causal flash attention (BQ=128, triple-buffered K/V) -> fp16
    dim3 g2(NH, S_LEN / BQ);
    flash16_kernel<<<g2, 256, FSMEM>>>(qkvh, qkvl, at16);

    // 3. Output projection (single fp16) -> fp32 out
    dim3 g3(S_LEN / MT, HID / NT);
    gemm16p<false, false><<<g3, 256, GEMM_SMEM_SINGLE>>>(
        at16, wo16, nullptr, out, nullptr, nullptr, S_LEN, HID, HID);
}

// round 11
// speedup vs baseline: 1.4443x; 1.4443x over previous
#include <cuda_runtime.h>
#include <cuda_fp16.h>
#include <cstdint>
#include <math.h>

#define S_LEN 2048
#define HID   5120
#define NH    40
#define HD    128
#define QKV_N (3*HID)   // 15360

// ---- fp16 mma GEMM tiling (R9-proven padded layout) ----
#define MT 128
#define NT 128
#define KT 32
#define BSTR 40                         // halves per smem row (32 data + 8 pad)
#define TILE_BYTES (128*BSTR*2)         // 10240 per operand tile
#define STAGE_SPLIT  (3*TILE_BYTES)     // A + Bhi + Blo = 30720
#define STAGE_SINGLE (2*TILE_BYTES)     // A + B        = 20480
#define STAGES_SPLIT  3
#define STAGES_SINGLE 4
#define GEMM_SMEM_SPLIT  (STAGES_SPLIT*STAGE_SPLIT)     // 92160
#define GEMM_SMEM_SINGLE (STAGES_SINGLE*STAGE_SINGLE)   // 81920

// ---- flash-attention (fp16 tensor, BQ=128, triple-buffered K/V) ----
#define BQ 128
#define BKV 64
#define AQS 136                          // halves stride for 128-wide rows
#define KV_TILE (BKV*AQS*2)              // 17408
#define Q_TILE  (BQ*AQS*2)               // 34816
#define KVBUF   (3*KV_TILE)              // Kh,Kl,Vh = 52224
#define KV_STAGES 3
#define FSMEM   (2*Q_TILE + KV_STAGES*KVBUF)   // 226304

// Scratch (allocation-free rule: __device__ globals)
__device__ __half g_qkvh[(size_t)S_LEN * QKV_N];       // QKV hi fp16
__device__ __half g_qkvl[(size_t)S_LEN * QKV_N];       // QKV lo fp16 (Q,K only)
__device__ __half g_h16[(size_t)S_LEN * HID];          // hidden fp16
__device__ __half g_wp_hi[(size_t)QKV_N * HID];        // Wpack hi (K,V rows plain)
__device__ __half g_wp_lo[(size_t)QKV_N * HID];        // Wpack lo (Q rows only)
__device__ __half g_wo16[(size_t)HID * HID];           // Wo fp16
__device__ __half g_attno16[(size_t)S_LEN * HID];      // attention out fp16

// ============================================================================
// PTX helpers
// ============================================================================
__device__ __forceinline__ uint32_t smem_u32(const void* p) {
    uint32_t a;
    asm("{ .reg .u64 t; cvta.to.shared.u64 t, %1; cvt.u32.u64 %0, t; }"
        : "=r"(a) : "l"(p));
    return a;
}

__device__ __forceinline__ void ldsm4(uint32_t* r, uint32_t a) {
    asm volatile("ldmatrix.sync.aligned.m8n8.x4.shared.b16 {%0,%1,%2,%3}, [%4];"
                 : "=r"(r[0]), "=r"(r[1]), "=r"(r[2]), "=r"(r[3]) : "r"(a));
}
__device__ __forceinline__ void ldsm4t(uint32_t* r, uint32_t a) {
    asm volatile("ldmatrix.sync.aligned.m8n8.x4.trans.shared.b16 {%0,%1,%2,%3}, [%4];"
                 : "=r"(r[0]), "=r"(r[1]), "=r"(r[2]), "=r"(r[3]) : "r"(a));
}

__device__ __forceinline__ void mma16(float* c, const uint32_t* a,
                                      uint32_t b0, uint32_t b1) {
    asm volatile(
        "mma.sync.aligned.m16n8k16.row.col.f32.f16.f16.f32 "
        "{%0,%1,%2,%3}, {%4,%5,%6,%7}, {%8,%9}, {%0,%1,%2,%3};"
        : "+f"(c[0]), "+f"(c[1]), "+f"(c[2]), "+f"(c[3])
        : "r"(a[0]), "r"(a[1]), "r"(a[2]), "r"(a[3]), "r"(b0), "r"(b1));
}

__device__ __forceinline__ uint32_t packh2(float a, float b) {
    __half2 h = __floats2half2_rn(a, b);
    return *reinterpret_cast<uint32_t*>(&h);
}

__device__ __forceinline__ void split4(const float4 v, uint2& hi, uint2& lo) {
    __half h0 = __float2half_rn(v.x), h1 = __float2half_rn(v.y);
    __half h2 = __float2half_rn(v.z), h3 = __float2half_rn(v.w);
    hi.x = packh2(v.x, v.y);
    hi.y = packh2(v.z, v.w);
    lo.x = packh2(v.x - __half2float(h0), v.y - __half2float(h1));
    lo.y = packh2(v.z - __half2float(h2), v.w - __half2float(h3));
}
__device__ __forceinline__ uint2 cvt4(const float4 v) {
    uint2 r; r.x = packh2(v.x, v.y); r.y = packh2(v.z, v.w); return r;
}

__device__ __forceinline__ void cpa16(uint32_t dst, const void* src) {
    asm volatile("cp.async.cg.shared.global [%0], [%1], 16;"
                 :: "r"(dst), "l"(src) : "memory");
}
__device__ __forceinline__ void cp_commit() {
    asm volatile("cp.async.commit_group;" ::: "memory");
}
template<int N> __device__ __forceinline__ void cp_wait() {
    asm volatile("cp.async.wait_group %0;" :: "n"(N) : "memory");
}

// ============================================================================
// Pre-conversion kernels
// ============================================================================
__global__ void cvt_split_kernel(const float4* __restrict__ in,
                                 uint2* __restrict__ hi, uint2* __restrict__ lo,
                                 int n4) {
    for (int i = blockIdx.x * blockDim.x + threadIdx.x; i < n4;
         i += gridDim.x * blockDim.x) {
        uint2 h, l; split4(in[i], h, l);
        hi[i] = h; lo[i] = l;
    }
}
// fused plain conversions: hidden, Wpack K+V rows, Wo
__global__ void cvt_fused3_kernel(const float4* __restrict__ a, uint2* __restrict__ ao, int na,
                                  const float4* __restrict__ b, uint2* __restrict__ bo, int nb,
                                  const float4* __restrict__ c, uint2* __restrict__ co, int nc) {
    const int tot = na + nb + nc;
    for (int i = blockIdx.x * blockDim.x + threadIdx.x; i < tot;
         i += gridDim.x * blockDim.x) {
        if (i < na) ao[i] = cvt4(a[i]);
        else if (i < na + nb) bo[i - na] = cvt4(b[i - na]);
        else co[i - na - nb] = cvt4(c[i - na - nb]);
    }
}

// ============================================================================
// fp16 tensor GEMM (TN), cp.async pipeline (R9 structure), 2 CTAs/SM.
// SPLITB: B = Bh + Bl only for Q tiles (n0 < HID); K,V tiles plain fp16.
// SPLITOUT: write hi/lo fp16 split of the fp32 accumulator (lo for Q,K only).
// ============================================================================
template<bool SPLITB, bool SPLITOUT>
__global__ __launch_bounds__(256, 2)
void gemm16p(const __half* __restrict__ A, const __half* __restrict__ Bh,
             const __half* __restrict__ Bl, float* __restrict__ Cf,
             __half* __restrict__ Chi, __half* __restrict__ Clo,
             int M, int N, int K) {
    extern __shared__ __align__(16) char sm[];
    const uint32_t sb = smem_u32(sm);
    constexpr uint32_t stageBytes = SPLITB ? STAGE_SPLIT : STAGE_SINGLE;
    constexpr int STAGES = SPLITB ? STAGES_SPLIT : STAGES_SINGLE;

    const int t   = threadIdx.x;
    const int wid = t >> 5;
    const int ln  = t & 31;
    const int m0  = blockIdx.x * MT;
    const int n0  = blockIdx.y * NT;
    const int wm  = (wid >> 1) * 32;
    const int wn  = (wid & 1) * 64;
    const bool useBl = SPLITB && (n0 < HID);   // Q tiles only (K,V plain)

    const int r0 = t >> 2;             // 0..63
    const int sg = t & 3;              // 0..3
    const __half* Ag0 = A  + (size_t)(m0 + r0) * K + sg * 8;
    const __half* Ag1 = Ag0 + (size_t)64 * K;
    const __half* Bh0 = Bh + (size_t)(n0 + r0) * K + sg * 8;
    const __half* Bh1 = Bh0 + (size_t)64 * K;
    const __half* Bl0 = SPLITB ? (Bl + (size_t)(n0 + r0) * K + sg * 8) : (const __half*)0;
    const __half* Bl1 = SPLITB ? (Bl0 + (size_t)64 * K) : (const __half*)0;
    const uint32_t d0 = (uint32_t)r0 * (BSTR * 2) + sg * 16;
    const uint32_t d1 = d0 + 64 * (BSTR * 2);

    const uint32_t aoff = ((uint32_t)(wm + (ln & 15)) * BSTR + 8u * (ln >> 4)) * 2;
    const uint32_t boff = TILE_BYTES +
        ((uint32_t)(wn + (ln & 7) + 8 * (ln >> 4)) * BSTR + 8u * ((ln >> 3) & 1)) * 2;

    float acc[2][8][4];
#pragma unroll
    for (int mi = 0; mi < 2; mi++)
#pragma unroll
        for (int nf = 0; nf < 8; nf++)
#pragma unroll
            for (int r = 0; r < 4; r++) acc[mi][nf][r] = 0.0f;

    const int NKT = K / KT;   // 160

    auto issue = [&](int st, int kt) {
        const uint32_t base = sb + (uint32_t)st * stageBytes;
        const size_t ko = (size_t)kt * KT;
        cpa16(base + d0, Ag0 + ko);
        cpa16(base + d1, Ag1 + ko);
        cpa16(base + TILE_BYTES + d0, Bh0 + ko);
        cpa16(base + TILE_BYTES + d1, Bh1 + ko);
        if (useBl) {
            cpa16(base + 2 * TILE_BYTES + d0, Bl0 + ko);
            cpa16(base + 2 * TILE_BYTES + d1, Bl1 + ko);
        }
    };

#pragma unroll
    for (int s = 0; s < STAGES - 1; s++) { issue(s, s); cp_commit(); }

#pragma unroll 1
    for (int kt = 0; kt < NKT; kt++) {
        cp_wait<STAGES - 2>();
        __syncthreads();

        const uint32_t so = sb + (uint32_t)(kt % STAGES) * stageBytes;
#pragma unroll
        for (int ks = 0; ks < 2; ks++) {
            const uint32_t ko = ks * 32;   // 16 halves
            uint32_t af[2][4];
            ldsm4(af[0], so + aoff + ko);
            ldsm4(af[1], so + aoff + 16 * BSTR * 2 + ko);
            uint32_t bh[4][4];
#pragma unroll
            for (int p = 0; p < 4; p++)
                ldsm4(bh[p], so + boff + p * (16 * BSTR * 2) + ko);
            uint32_t bl[4][4];
            if (useBl) {
#pragma unroll
                for (int p = 0; p < 4; p++)
                    ldsm4(bl[p], so + boff + TILE_BYTES + p * (16 * BSTR * 2) + ko);
            }
#pragma unroll
            for (int mi = 0; mi < 2; mi++)
#pragma unroll
                for (int nf = 0; nf < 8; nf++) {
                    mma16(acc[mi][nf], af[mi],
                          bh[nf >> 1][(nf & 1) * 2], bh[nf >> 1][(nf & 1) * 2 + 1]);
                    if (useBl)
                        mma16(acc[mi][nf], af[mi],
                              bl[nf >> 1][(nf & 1) * 2], bl[nf >> 1][(nf & 1) * 2 + 1]);
                }
        }

        const int nk = kt + STAGES - 1;
        if (nk < NKT) issue(nk % STAGES, nk);
        cp_commit();
    }

    // epilogue
    const bool writeLo = SPLITOUT && (n0 < 2 * HID);   // Q,K get hi/lo outputs
#pragma unroll
    for (int mi = 0; mi < 2; mi++) {
        const int r = m0 + wm + mi * 16 + (ln >> 2);
#pragma unroll
        for (int nf = 0; nf < 8; nf++) {
            const int cc = n0 + wn + nf * 8 + (ln & 3) * 2;
            if (SPLITOUT) {
#pragma unroll
                for (int hh = 0; hh < 2; hh++) {
                    const float v0 = acc[mi][nf][2 * hh], v1 = acc[mi][nf][2 * hh + 1];
                    const __half h0 = __float2half_rn(v0), h1 = __float2half_rn(v1);
                    const size_t off = (size_t)(r + 8 * hh) * N + cc;
                    *(uint32_t*)(Chi + off) = packh2(v0, v1);
                    if (writeLo)
                        *(uint32_t*)(Clo + off) =
                            packh2(v0 - __half2float(h0), v1 - __half2float(h1));
                }
            } else {
                *(float2*)(Cf + (size_t)r * N + cc) =
                    make_float2(acc[mi][nf][0], acc[mi][nf][1]);
                *(float2*)(Cf + (size_t)(r + 8) * N + cc) =
                    make_float2(acc[mi][nf][2], acc[mi][nf][3]);
            }
        }
    }
}

// ============================================================================
// Flash attention (R9/R8-proven), fp16 tensor, causal. BQ=128, 256 thr,
// triple-buffered K/V via cp.async; one sync per KV block; Q in registers.
// S = QhKh + QhKl + QlKh; O += P*Vh. Grid (NH, S/BQ) with qb reversed.
// ============================================================================
__global__ __launch_bounds__(256, 1)
void flash16_kernel(const __half* __restrict__ qh, const __half* __restrict__ ql,
                    __half* __restrict__ out) {
    extern __shared__ __align__(16) char sm[];
    const uint32_t sb = smem_u32(sm);
    const uint32_t uQh = sb;
    const uint32_t uQl = sb + Q_TILE;
    const uint32_t uBuf0 = sb + 2 * Q_TILE;

    const int head = blockIdx.x;
    const int qb   = (int)gridDim.y - 1 - (int)blockIdx.y;   // heavy first
    const int q0   = qb * BQ;
    const int t    = threadIdx.x;
    const int w    = t >> 5;
    const int ln   = t & 31;
    const int m0w  = w * 16;
    const float scale = 0.08838834764831845f;   // 1/sqrt(128)

    const int lr  = t >> 2;            // 0..63
    const int lc  = (t & 3) * 4;       // chunk base 0,4,8,12

    auto issueKV = [&](int kb) {
        const uint32_t base = uBuf0 + (uint32_t)(kb % KV_STAGES) * KVBUF;
        const size_t gk = (size_t)(kb * BKV + lr) * QKV_N + HID + head * HD;
        const size_t gv = gk + HID;
        const uint32_t ro = (uint32_t)lr * (AQS * 2);
#pragma unroll
        for (int i = 0; i < 4; i++) {
            const int c = lc + i;
            cpa16(base + ro + c * 16, qh + gk + c * 8);                    // Kh
            cpa16(base + KV_TILE + ro + c * 16, ql + gk + c * 8);          // Kl
            cpa16(base + 2 * KV_TILE + ro + c * 16, qh + gv + c * 8);      // Vh
        }
    };

    // ---- prologue: Q + KV0 as one group, KV1 as second ----
#pragma unroll
    for (int pass = 0; pass < 2; pass++) {
        const int r = pass * 64 + lr;
        const size_t go = (size_t)(q0 + r) * QKV_N + head * HD;
        const uint32_t ro = (uint32_t)r * (AQS * 2);
#pragma unroll
        for (int i = 0; i < 4; i++) {
            const int c = lc + i;
            cpa16(uQh + ro + c * 16, qh + go + c * 8);
            cpa16(uQl + ro + c * 16, ql + go + c * 8);
        }
    }
    issueKV(0);
    cp_commit();          // group: Q + KV0
    issueKV(1);
    cp_commit();          // group: KV1

    const int nkb = 2 * (qb + 1);

    cp_wait<1>();         // Q + KV0 ready
    __syncthreads();

    // ---- hoist Q fragments (hi/lo) to registers ----
    const uint32_t aQ = ((uint32_t)(m0w + (ln & 15)) * AQS + 8u * (ln >> 4)) * 2;
    uint32_t qhf[8][4], qlf[8][4];
#pragma unroll
    for (int ks = 0; ks < 8; ks++) {
        ldsm4(qhf[ks], uQh + aQ + ks * 32);
        ldsm4(qlf[ks], uQl + aQ + ks * 32);
    }

    float m_i[2] = {-1e30f, -1e30f};
    float l_i[2] = {0.0f, 0.0f};
    float o[16][4];
#pragma unroll
    for (int d = 0; d < 16; d++)
#pragma unroll
        for (int r = 0; r < 4; r++) o[d][r] = 0.0f;

    const uint32_t bK = ((uint32_t)((ln & 7) + 8 * (ln >> 4)) * AQS + 8u * ((ln >> 3) & 1)) * 2;
    const uint32_t bV = ((uint32_t)((ln & 7) + 8 * ((ln >> 3) & 1)) * AQS + 8u * (ln >> 4)) * 2;

    const int r1g = q0 + m0w + (ln >> 2);
    const int r2g = r1g + 8;

#pragma unroll 1
    for (int kb = 0; kb < nkb; kb++) {
        const int k0 = kb * BKV;

        if (kb + 2 < nkb) issueKV(kb + 2);
        cp_commit();

        if (k0 <= q0 + m0w + 15) {
            const uint32_t cKh = uBuf0 + (uint32_t)(kb % KV_STAGES) * KVBUF;
            const uint32_t cKl = cKh + KV_TILE;
            const uint32_t cVh = cKh + 2 * KV_TILE;

            float s[8][4];
#pragma unroll
            for (int nf = 0; nf < 8; nf++)
#pragma unroll
                for (int r = 0; r < 4; r++) s[nf][r] = 0.0f;

#pragma unroll
            for (int ks = 0; ks < 8; ks++) {
                const uint32_t ko = ks * 32;
                uint32_t kh[4][4], kl[4][4];
#pragma unroll
                for (int p = 0; p < 4; p++) {
                    ldsm4(kh[p], cKh + bK + p * (16 * AQS * 2) + ko);
                    ldsm4(kl[p], cKl + bK + p * (16 * AQS * 2) + ko);
                }
#pragma unroll
                for (int nf = 0; nf < 8; nf++) {
                    const uint32_t h0 = kh[nf >> 1][(nf & 1) * 2];
                    const uint32_t h1 = kh[nf >> 1][(nf & 1) * 2 + 1];
                    const uint32_t l0 = kl[nf >> 1][(nf & 1) * 2];
                    const uint32_t l1 = kl[nf >> 1][(nf & 1) * 2 + 1];
                    mma16(s[nf], qhf[ks], h0, h1);
                    mma16(s[nf], qhf[ks], l0, l1);
                    mma16(s[nf], qlf[ks], h0, h1);
                }
            }

            const bool needMask = (k0 + BKV - 1 > q0 + m0w);
            float mx1 = -1e30f, mx2 = -1e30f;
#pragma unroll
            for (int nf = 0; nf < 8; nf++) {
                float v0 = s[nf][0] * scale, v1 = s[nf][1] * scale;
                float v2 = s[nf][2] * scale, v3 = s[nf][3] * scale;
                if (needMask) {
                    const int cb = k0 + nf * 8 + 2 * (ln & 3);
                    if (cb     > r1g) v0 = -1e30f;
                    if (cb + 1 > r1g) v1 = -1e30f;
                    if (cb     > r2g) v2 = -1e30f;
                    if (cb + 1 > r2g) v3 = -1e30f;
                }
                s[nf][0] = v0; s[nf][1] = v1; s[nf][2] = v2; s[nf][3] = v3;
                mx1 = fmaxf(mx1, fmaxf(v0, v1));
                mx2 = fmaxf(mx2, fmaxf(v2, v3));
            }
            mx1 = fmaxf(mx1, __shfl_xor_sync(0xffffffffu, mx1, 1));
            mx1 = fmaxf(mx1, __shfl_xor_sync(0xffffffffu, mx1, 2));
            mx2 = fmaxf(mx2, __shfl_xor_sync(0xffffffffu, mx2, 1));
            mx2 = fmaxf(mx2, __shfl_xor_sync(0xffffffffu, mx2, 2));

            const float mn1 = fmaxf(m_i[0], mx1);
            const float mn2 = fmaxf(m_i[1], mx2);
            const float corr1 = __expf(m_i[0] - mn1);
            const float corr2 = __expf(m_i[1] - mn2);
            m_i[0] = mn1; m_i[1] = mn2;

            float rs1 = 0.0f, rs2 = 0.0f;
#pragma unroll
            for (int nf = 0; nf < 8; nf++) {
                float p0 = __expf(s[nf][0] - mn1);
                float p1 = __expf(s[nf][1] - mn1);
                float p2 = __expf(s[nf][2] - mn2);
                float p3 = __expf(s[nf][3] - mn2);
                rs1 += p0 + p1; rs2 += p2 + p3;
                s[nf][0] = p0; s[nf][1] = p1; s[nf][2] = p2; s[nf][3] = p3;
            }
            rs1 += __shfl_xor_sync(0xffffffffu, rs1, 1);
            rs1 += __shfl_xor_sync(0xffffffffu, rs1, 2);
            rs2 += __shfl_xor_sync(0xffffffffu, rs2, 1);
            rs2 += __shfl_xor_sync(0xffffffffu, rs2, 2);
            l_i[0] = l_i[0] * corr1 + rs1;
            l_i[1] = l_i[1] * corr2 + rs2;

#pragma unroll
            for (int d = 0; d < 16; d++) {
                o[d][0] *= corr1; o[d][1] *= corr1;
                o[d][2] *= corr2; o[d][3] *= corr2;
            }

            uint32_t pa[4][4];
#pragma unroll
            for (int tk = 0; tk < 4; tk++) {
                pa[tk][0] = packh2(s[2 * tk][0],     s[2 * tk][1]);
                pa[tk][1] = packh2(s[2 * tk][2],     s[2 * tk][3]);
                pa[tk][2] = packh2(s[2 * tk + 1][0], s[2 * tk + 1][1]);
                pa[tk][3] = packh2(s[2 * tk + 1][2], s[2 * tk + 1][3]);
            }

#pragma unroll
            for (int tk = 0; tk < 4; tk++) {
                const uint32_t rowo = (uint32_t)(16 * tk) * AQS * 2;
#pragma unroll
                for (int p = 0; p < 8; p++) {
                    uint32_t vh[4];
                    ldsm4t(vh, cVh + rowo + bV + (uint32_t)p * 32);
                    mma16(o[2 * p],     pa[tk], vh[0], vh[1]);
                    mma16(o[2 * p + 1], pa[tk], vh[2], vh[3]);
                }
            }
        }

        if (kb + 1 < nkb) {
            cp_wait<1>();      // next block's K/V landed
            __syncthreads();   // single barrier per iteration
        }
    }

    // ---- epilogue: fp16 output ----
    const float inv1 = 1.0f / l_i[0];
    const float inv2 = 1.0f / l_i[1];
#pragma unroll
    for (int d = 0; d < 16; d++) {
        const int cc = head * HD + d * 8 + 2 * (ln & 3);
        *(__half2*)(out + (size_t)r1g * HID + cc) =
            __floats2half2_rn(o[d][0] * inv1, o[d][1] * inv1);
        *(__half2*)(out + (size_t)r2g * HID + cc) =
            __floats2half2_rn(o[d][2] * inv2, o[d][3] * inv2);
    }
}

// ============================================================================
// Launch
// ============================================================================
extern "C" void kernel_launch(void* const* d_in, const int* in_sizes, int n_in,
                              void* d_out, int out_size) {
    const float* hidden = (const float*)d_in[0];
    const float* wpack  = (const float*)d_in[1];
    const float* wo     = (const float*)d_in[2];
    float* out = (float*)d_out;

    __half *qkvh, *qkvl, *h16, *wph, *wpl, *wo16, *at16;
    cudaGetSymbolAddress((void**)&qkvh, g_qkvh);
    cudaGetSymbolAddress((void**)&qkvl, g_qkvl);
    cudaGetSymbolAddress((void**)&h16,  g_h16);
    cudaGetSymbolAddress((void**)&wph,  g_wp_hi);
    cudaGetSymbolAddress((void**)&wpl,  g_wp_lo);
    cudaGetSymbolAddress((void**)&wo16, g_wo16);
    cudaGetSymbolAddress((void**)&at16, g_attno16);

    cudaFuncSetAttribute((const void*)gemm16p<true, true>,
                         cudaFuncAttributeMaxDynamicSharedMemorySize, GEMM_SMEM_SPLIT);
    cudaFuncSetAttribute((const void*)gemm16p<false, false>,
                         cudaFuncAttributeMaxDynamicSharedMemorySize, GEMM_SMEM_SINGLE);
    cudaFuncSetAttribute((const void*)flash16_kernel,
                         cudaFuncAttributeMaxDynamicSharedMemorySize, FSMEM);

    // 0. pre-conversions: Wpack Q rows -> hi/lo split; H, Wpack K+V rows, Wo -> fp16
    const size_t qRows  = (size_t)HID * HID;       // first 5120 rows of Wpack (Q)
    const size_t kvRows = (size_t)2 * HID * HID;   // K+V rows of Wpack
    cvt_split_kernel<<<8192, 256>>>((const float4*)wpack, (uint2*)wph, (uint2*)wpl,
                                    (int)(qRows / 4));
    cvt_fused3_kernel<<<8192, 256>>>(
        (const float4*)hidden, (uint2*)h16, (int)((size_t)S_LEN * HID / 4),
        (const float4*)(wpack + qRows), (uint2*)(wph + qRows),
        (int)(kvRows / 4),
        (const float4*)wo, (uint2*)wo16, (int)((size_t)HID * HID / 4));

    // 1. QKV projection (split-B for Q tiles only; split-out hi/lo for Q,K)
    dim3 g1(S_LEN / MT, QKV_N / NT);
    gemm16p<true, true><<<g1, 256, GEMM_SMEM_SPLIT>>>(
        h16, wph, wpl, nullptr, qkvh, qkvl, S_LEN, QKV_N, HID);

    // 2. Causal flash attention (BQ=128, triple-buffered K/V) -> fp16
    dim3 g2(NH, S_LEN / BQ);
    flash16_kernel<<<g2, 256, FSMEM>>>(qkvh, qkvl, at16);

    // 3. Output projection (single fp16) -> fp32 out
    dim3 g3(S_LEN / MT, HID / NT);
    gemm16p<false, false><<<g3, 256, GEMM_SMEM_SINGLE>>>(
        at16, wo16, nullptr, out, nullptr, nullptr, S_LEN, HID, HID);
}

// round 12
// speedup vs baseline: 2.0214x; 1.3996x over previous
#include <cuda_runtime.h>
#include <cuda_fp16.h>
#include <cstdint>
#include <math.h>

#define S_LEN 2048
#define HID   5120
#define NH    40
#define HD    128
#define QKV_N (3*HID)   // 15360

// ---- fp16 mma GEMM tiling (R9-proven padded layout) ----
#define MT 128
#define NT 128
#define KT 32
#define BSTR 40                         // halves per smem row (32 data + 8 pad)
#define TILE_BYTES (128*BSTR*2)         // 10240 per operand tile
#define STAGE_SINGLE (2*TILE_BYTES)     // A + B = 20480
#define STAGES_SINGLE 4
#define GEMM_SMEM_SINGLE (STAGES_SINGLE*STAGE_SINGLE)   // 81920 (x2 CTA = 163840)

// ---- flash-attention (fp16 tensor, BQ=128, triple-buffered K/V) ----
#define BQ 128
#define BKV 64
#define AQS 136                          // halves stride for 128-wide rows
#define KV_TILE (BKV*AQS*2)              // 17408
#define Q_TILE  (BQ*AQS*2)               // 34816
#define KVBUF   (3*KV_TILE)              // Kh,Kl,Vh = 52224
#define KV_STAGES 3
#define FSMEM   (2*Q_TILE + KV_STAGES*KVBUF)   // 226304

// Scratch (allocation-free rule: __device__ globals)
__device__ __half g_qkvh[(size_t)S_LEN * QKV_N];       // QKV hi fp16
__device__ __half g_qkvl[(size_t)S_LEN * QKV_N];       // QKV lo fp16 (Q,K only)
__device__ __half g_h16[(size_t)S_LEN * HID];          // hidden fp16
__device__ __half g_wp16[(size_t)QKV_N * HID];         // Wpack fp16 (plain)
__device__ __half g_wo16[(size_t)HID * HID];           // Wo fp16
__device__ __half g_attno16[(size_t)S_LEN * HID];      // attention out fp16

// ============================================================================
// PTX helpers
// ============================================================================
__device__ __forceinline__ uint32_t smem_u32(const void* p) {
    uint32_t a;
    asm("{ .reg .u64 t; cvta.to.shared.u64 t, %1; cvt.u32.u64 %0, t; }"
        : "=r"(a) : "l"(p));
    return a;
}

__device__ __forceinline__ void ldsm4(uint32_t* r, uint32_t a) {
    asm volatile("ldmatrix.sync.aligned.m8n8.x4.shared.b16 {%0,%1,%2,%3}, [%4];"
                 : "=r"(r[0]), "=r"(r[1]), "=r"(r[2]), "=r"(r[3]) : "r"(a));
}
__device__ __forceinline__ void ldsm4t(uint32_t* r, uint32_t a) {
    asm volatile("ldmatrix.sync.aligned.m8n8.x4.trans.shared.b16 {%0,%1,%2,%3}, [%4];"
                 : "=r"(r[0]), "=r"(r[1]), "=r"(r[2]), "=r"(r[3]) : "r"(a));
}

__device__ __forceinline__ void mma16(float* c, const uint32_t* a,
                                      uint32_t b0, uint32_t b1) {
    asm volatile(
        "mma.sync.aligned.m16n8k16.row.col.f32.f16.f16.f32 "
        "{%0,%1,%2,%3}, {%4,%5,%6,%7}, {%8,%9}, {%0,%1,%2,%3};"
        : "+f"(c[0]), "+f"(c[1]), "+f"(c[2]), "+f"(c[3])
        : "r"(a[0]), "r"(a[1]), "r"(a[2]), "r"(a[3]), "r"(b0), "r"(b1));
}

__device__ __forceinline__ uint32_t packh2(float a, float b) {
    __half2 h = __floats2half2_rn(a, b);
    return *reinterpret_cast<uint32_t*>(&h);
}

__device__ __forceinline__ uint2 cvt4(const float4 v) {
    uint2 r; r.x = packh2(v.x, v.y); r.y = packh2(v.z, v.w); return r;
}

__device__ __forceinline__ void cpa16(uint32_t dst, const void* src) {
    asm volatile("cp.async.cg.shared.global [%0], [%1], 16;"
                 :: "r"(dst), "l"(src) : "memory");
}
__device__ __forceinline__ void cp_commit() {
    asm volatile("cp.async.commit_group;" ::: "memory");
}
template<int N> __device__ __forceinline__ void cp_wait() {
    asm volatile("cp.async.wait_group %0;" :: "n"(N) : "memory");
}

// ============================================================================
// Pre-conversion: fused plain conversions (hidden, Wpack full, Wo)
// ============================================================================
__global__ void cvt_fused3_kernel(const float4* __restrict__ a, uint2* __restrict__ ao, int na,
                                  const float4* __restrict__ b, uint2* __restrict__ bo, int nb,
                                  const float4* __restrict__ c, uint2* __restrict__ co, int nc) {
    const int tot = na + nb + nc;
    for (int i = blockIdx.x * blockDim.x + threadIdx.x; i < tot;
         i += gridDim.x * blockDim.x) {
        if (i < na) ao[i] = cvt4(a[i]);
        else if (i < na + nb) bo[i - na] = cvt4(b[i - na]);
        else co[i - na - nb] = cvt4(c[i - na - nb]);
    }
}

// ============================================================================
// fp16 tensor GEMM (TN), plain B, 4-stage cp.async pipeline (R9 structure),
// 2 CTAs/SM.
// SPLITOUT: write hi/lo fp16 split of the fp32 accumulator (lo for n0<2*HID,
//           i.e. Q and K outputs; V gets hi only).
// ============================================================================
template<bool SPLITOUT>
__global__ __launch_bounds__(256, 2)
void gemm16p(const __half* __restrict__ A, const __half* __restrict__ Bh,
             float* __restrict__ Cf,
             __half* __restrict__ Chi, __half* __restrict__ Clo,
             int M, int N, int K) {
    extern __shared__ __align__(16) char sm[];
    const uint32_t sb = smem_u32(sm);
    constexpr uint32_t stageBytes = STAGE_SINGLE;
    constexpr int STAGES = STAGES_SINGLE;

    const int t   = threadIdx.x;
    const int wid = t >> 5;
    const int ln  = t & 31;
    const int m0  = blockIdx.x * MT;
    const int n0  = blockIdx.y * NT;
    const int wm  = (wid >> 1) * 32;
    const int wn  = (wid & 1) * 64;

    const int r0 = t >> 2;             // 0..63
    const int sg = t & 3;              // 0..3
    const __half* Ag0 = A  + (size_t)(m0 + r0) * K + sg * 8;
    const __half* Ag1 = Ag0 + (size_t)64 * K;
    const __half* Bh0 = Bh + (size_t)(n0 + r0) * K + sg * 8;
    const __half* Bh1 = Bh0 + (size_t)64 * K;
    const uint32_t d0 = (uint32_t)r0 * (BSTR * 2) + sg * 16;
    const uint32_t d1 = d0 + 64 * (BSTR * 2);

    const uint32_t aoff = ((uint32_t)(wm + (ln & 15)) * BSTR + 8u * (ln >> 4)) * 2;
    const uint32_t boff = TILE_BYTES +
        ((uint32_t)(wn + (ln & 7) + 8 * (ln >> 4)) * BSTR + 8u * ((ln >> 3) & 1)) * 2;

    float acc[2][8][4];
#pragma unroll
    for (int mi = 0; mi < 2; mi++)
#pragma unroll
        for (int nf = 0; nf < 8; nf++)
#pragma unroll
            for (int r = 0; r < 4; r++) acc[mi][nf][r] = 0.0f;

    const int NKT = K / KT;   // 160

    auto issue = [&](int st, int kt) {
        const uint32_t base = sb + (uint32_t)st * stageBytes;
        const size_t ko = (size_t)kt * KT;
        cpa16(base + d0, Ag0 + ko);
        cpa16(base + d1, Ag1 + ko);
        cpa16(base + TILE_BYTES + d0, Bh0 + ko);
        cpa16(base + TILE_BYTES + d1, Bh1 + ko);
    };

#pragma unroll
    for (int s = 0; s < STAGES - 1; s++) { issue(s, s); cp_commit(); }

#pragma unroll 1
    for (int kt = 0; kt < NKT; kt++) {
        cp_wait<STAGES - 2>();
        __syncthreads();

        const uint32_t so = sb + (uint32_t)(kt % STAGES) * stageBytes;
#pragma unroll
        for (int ks = 0; ks < 2; ks++) {
            const uint32_t ko = ks * 32;   // 16 halves
            uint32_t af[2][4];
            ldsm4(af[0], so + aoff + ko);
            ldsm4(af[1], so + aoff + 16 * BSTR * 2 + ko);
            uint32_t bh[4][4];
#pragma unroll
            for (int p = 0; p < 4; p++)
                ldsm4(bh[p], so + boff + p * (16 * BSTR * 2) + ko);
#pragma unroll
            for (int mi = 0; mi < 2; mi++)
#pragma unroll
                for (int nf = 0; nf < 8; nf++)
                    mma16(acc[mi][nf], af[mi],
                          bh[nf >> 1][(nf & 1) * 2], bh[nf >> 1][(nf & 1) * 2 + 1]);
        }

        const int nk = kt + STAGES - 1;
        if (nk < NKT) issue(nk % STAGES, nk);
        cp_commit();
    }

    // epilogue
    const bool writeLo = SPLITOUT && (n0 < 2 * HID);   // Q,K get hi/lo outputs
#pragma unroll
    for (int mi = 0; mi < 2; mi++) {
        const int r = m0 + wm + mi * 16 + (ln >> 2);
#pragma unroll
        for (int nf = 0; nf < 8; nf++) {
            const int cc = n0 + wn + nf * 8 + (ln & 3) * 2;
            if (SPLITOUT) {
#pragma unroll
                for (int hh = 0; hh < 2; hh++) {
                    const float v0 = acc[mi][nf][2 * hh], v1 = acc[mi][nf][2 * hh + 1];
                    const __half h0 = __float2half_rn(v0), h1 = __float2half_rn(v1);
                    const size_t off = (size_t)(r + 8 * hh) * N + cc;
                    *(uint32_t*)(Chi + off) = packh2(v0, v1);
                    if (writeLo)
                        *(uint32_t*)(Clo + off) =
                            packh2(v0 - __half2float(h0), v1 - __half2float(h1));
                }
            } else {
                *(float2*)(Cf + (size_t)r * N + cc) =
                    make_float2(acc[mi][nf][0], acc[mi][nf][1]);
                *(float2*)(Cf + (size_t)(r + 8) * N + cc) =
                    make_float2(acc[mi][nf][2], acc[mi][nf][3]);
            }
        }
    }
}

// ============================================================================
// Flash attention (R9/R8-proven, unchanged), fp16 tensor, causal. BQ=128,
// 256 thr, triple-buffered K/V via cp.async; one sync per KV block; Q in regs.
// S = QhKh + QhKl + QlKh; O += P*Vh. Grid (NH, S/BQ) with qb reversed.
// ============================================================================
__global__ __launch_bounds__(256, 1)
void flash16_kernel(const __half* __restrict__ qh, const __half* __restrict__ ql,
                    __half* __restrict__ out) {
    extern __shared__ __align__(16) char sm[];
    const uint32_t sb = smem_u32(sm);
    const uint32_t uQh = sb;
    const uint32_t uQl = sb + Q_TILE;
    const uint32_t uBuf0 = sb + 2 * Q_TILE;

    const int head = blockIdx.x;
    const int qb   = (int)gridDim.y - 1 - (int)blockIdx.y;   // heavy first
    const int q0   = qb * BQ;
    const int t    = threadIdx.x;
    const int w    = t >> 5;
    const int ln   = t & 31;
    const int m0w  = w * 16;
    const float scale = 0.08838834764831845f;   // 1/sqrt(128)

    const int lr  = t >> 2;            // 0..63
    const int lc  = (t & 3) * 4;       // chunk base 0,4,8,12

    auto issueKV = [&](int kb) {
        const uint32_t base = uBuf0 + (uint32_t)(kb % KV_STAGES) * KVBUF;
        const size_t gk = (size_t)(kb * BKV + lr) * QKV_N + HID + head * HD;
        const size_t gv = gk + HID;
        const uint32_t ro = (uint32_t)lr * (AQS * 2);
#pragma unroll
        for (int i = 0; i < 4; i++) {
            const int c = lc + i;
            cpa16(base + ro + c * 16, qh + gk + c * 8);                    // Kh
            cpa16(base + KV_TILE + ro + c * 16, ql + gk + c * 8);          // Kl
            cpa16(base + 2 * KV_TILE + ro + c * 16, qh + gv + c * 8);      // Vh
        }
    };

    // ---- prologue: Q + KV0 as one group, KV1 as second ----
#pragma unroll
    for (int pass = 0; pass < 2; pass++) {
        const int r = pass * 64 + lr;
        const size_t go = (size_t)(q0 + r) * QKV_N + head * HD;
        const uint32_t ro = (uint32_t)r * (AQS * 2);
#pragma unroll
        for (int i = 0; i < 4; i++) {
            const int c = lc + i;
            cpa16(uQh + ro + c * 16, qh + go + c * 8);
            cpa16(uQl + ro + c * 16, ql + go + c * 8);
        }
    }
    issueKV(0);
    cp_commit();          // group: Q + KV0
    issueKV(1);
    cp_commit();          // group: KV1

    const int nkb = 2 * (qb + 1);

    cp_wait<1>();         // Q + KV0 ready
    __syncthreads();

    // ---- hoist Q fragments (hi/lo) to registers ----
    const uint32_t aQ = ((uint32_t)(m0w + (ln & 15)) * AQS + 8u * (ln >> 4)) * 2;
    uint32_t qhf[8][4], qlf[8][4];
#pragma unroll
    for (int ks = 0; ks < 8; ks++) {
        ldsm4(qhf[ks], uQh + aQ + ks * 32);
        ldsm4(qlf[ks], uQl + aQ + ks * 32);
    }

    float m_i[2] = {-1e30f, -1e30f};
    float l_i[2] = {0.0f, 0.0f};
    float o[16][4];
#pragma unroll
    for (int d = 0; d < 16; d++)
#pragma unroll
        for (int r = 0; r < 4; r++) o[d][r] = 0.0f;

    const uint32_t bK = ((uint32_t)((ln & 7) + 8 * (ln >> 4)) * AQS + 8u * ((ln >> 3) & 1)) * 2;
    const uint32_t bV = ((uint32_t)((ln & 7) + 8 * ((ln >> 3) & 1)) * AQS + 8u * (ln >> 4)) * 2;

    const int r1g = q0 + m0w + (ln >> 2);
    const int r2g = r1g + 8;

#pragma unroll 1
    for (int kb = 0; kb < nkb; kb++) {
        const int k0 = kb * BKV;

        if (kb + 2 < nkb) issueKV(kb + 2);
        cp_commit();

        if (k0 <= q0 + m0w + 15) {
            const uint32_t cKh = uBuf0 + (uint32_t)(kb % KV_STAGES) * KVBUF;
            const uint32_t cKl = cKh + KV_TILE;
            const uint32_t cVh = cKh + 2 * KV_TILE;

            float s[8][4];
#pragma unroll
            for (int nf = 0; nf < 8; nf++)
#pragma unroll
                for (int r = 0; r < 4; r++) s[nf][r] = 0.0f;

#pragma unroll
            for (int ks = 0; ks < 8; ks++) {
                const uint32_t ko = ks * 32;
                uint32_t kh[4][4], kl[4][4];
#pragma unroll
                for (int p = 0; p < 4; p++) {
                    ldsm4(kh[p], cKh + bK + p * (16 * AQS * 2) + ko);
                    ldsm4(kl[p], cKl + bK + p * (16 * AQS * 2) + ko);
                }
#pragma unroll
                for (int nf = 0; nf < 8; nf++) {
                    const uint32_t h0 = kh[nf >> 1][(nf & 1) * 2];
                    const uint32_t h1 = kh[nf >> 1][(nf & 1) * 2 + 1];
                    const uint32_t l0 = kl[nf >> 1][(nf & 1) * 2];
                    const uint32_t l1 = kl[nf >> 1][(nf & 1) * 2 + 1];
                    mma16(s[nf], qhf[ks], h0, h1);
                    mma16(s[nf], qhf[ks], l0, l1);
                    mma16(s[nf], qlf[ks], h0, h1);
                }
            }

            const bool needMask = (k0 + BKV - 1 > q0 + m0w);
            float mx1 = -1e30f, mx2 = -1e30f;
#pragma unroll
            for (int nf = 0; nf < 8; nf++) {
                float v0 = s[nf][0] * scale, v1 = s[nf][1] * scale;
                float v2 = s[nf][2] * scale, v3 = s[nf][3] * scale;
                if (needMask) {
                    const int cb = k0 + nf * 8 + 2 * (ln & 3);
                    if (cb     > r1g) v0 = -1e30f;
                    if (cb + 1 > r1g) v1 = -1e30f;
                    if (cb     > r2g) v2 = -1e30f;
                    if (cb + 1 > r2g) v3 = -1e30f;
                }
                s[nf][0] = v0; s[nf][1] = v1; s[nf][2] = v2; s[nf][3] = v3;
                mx1 = fmaxf(mx1, fmaxf(v0, v1));
                mx2 = fmaxf(mx2, fmaxf(v2, v3));
            }
            mx1 = fmaxf(mx1, __shfl_xor_sync(0xffffffffu, mx1, 1));
            mx1 = fmaxf(mx1, __shfl_xor_sync(0xffffffffu, mx1, 2));
            mx2 = fmaxf(mx2, __shfl_xor_sync(0xffffffffu, mx2, 1));
            mx2 = fmaxf(mx2, __shfl_xor_sync(0xffffffffu, mx2, 2));

            const float mn1 = fmaxf(m_i[0], mx1);
            const float mn2 = fmaxf(m_i[1], mx2);
            const float corr1 = __expf(m_i[0] - mn1);
            const float corr2 = __expf(m_i[1] - mn2);
            m_i[0] = mn1; m_i[1] = mn2;

            float rs1 = 0.0f, rs2 = 0.0f;
#pragma unroll
            for (int nf = 0; nf < 8; nf++) {
                float p0 = __expf(s[nf][0] - mn1);
                float p1 = __expf(s[nf][1] - mn1);
                float p2 = __expf(s[nf][2] - mn2);
                float p3 = __expf(s[nf][3] - mn2);
                rs1 += p0 + p1; rs2 += p2 + p3;
                s[nf][0] = p0; s[nf][1] = p1; s[nf][2] = p2; s[nf][3] = p3;
            }
            rs1 += __shfl_xor_sync(0xffffffffu, rs1, 1);
            rs1 += __shfl_xor_sync(0xffffffffu, rs1, 2);
            rs2 += __shfl_xor_sync(0xffffffffu, rs2, 1);
            rs2 += __shfl_xor_sync(0xffffffffu, rs2, 2);
            l_i[0] = l_i[0] * corr1 + rs1;
            l_i[1] = l_i[1] * corr2 + rs2;

#pragma unroll
            for (int d = 0; d < 16; d++) {
                o[d][0] *= corr1; o[d][1] *= corr1;
                o[d][2] *= corr2; o[d][3] *= corr2;
            }

            uint32_t pa[4][4];
#pragma unroll
            for (int tk = 0; tk < 4; tk++) {
                pa[tk][0] = packh2(s[2 * tk][0],     s[2 * tk][1]);
                pa[tk][1] = packh2(s[2 * tk][2],     s[2 * tk][3]);
                pa[tk][2] = packh2(s[2 * tk + 1][0], s[2 * tk + 1][1]);
                pa[tk][3] = packh2(s[2 * tk + 1][2], s[2 * tk + 1][3]);
            }

#pragma unroll
            for (int tk = 0; tk < 4; tk++) {
                const uint32_t rowo = (uint32_t)(16 * tk) * AQS * 2;
#pragma unroll
                for (int p = 0; p < 8; p++) {
                    uint32_t vh[4];
                    ldsm4t(vh, cVh + rowo + bV + (uint32_t)p * 32);
                    mma16(o[2 * p],     pa[tk], vh[0], vh[1]);
                    mma16(o[2 * p + 1], pa[tk], vh[2], vh[3]);
                }
            }
        }

        if (kb + 1 < nkb) {
            cp_wait<1>();      // next block's K/V landed
            __syncthreads();   // single barrier per iteration
        }
    }

    // ---- epilogue: fp16 output ----
    const float inv1 = 1.0f / l_i[0];
    const float inv2 = 1.0f / l_i[1];
#pragma unroll
    for (int d = 0; d < 16; d++) {
        const int cc = head * HD + d * 8 + 2 * (ln & 3);
        *(__half2*)(out + (size_t)r1g * HID + cc) =
            __floats2half2_rn(o[d][0] * inv1, o[d][1] * inv1);
        *(__half2*)(out + (size_t)r2g * HID + cc) =
            __floats2half2_rn(o[d][2] * inv2, o[d][3] * inv2);
    }
}

// ============================================================================
// Launch
// ============================================================================
extern "C" void kernel_launch(void* const* d_in, const int* in_sizes, int n_in,
                              void* d_out, int out_size) {
    const float* hidden = (const float*)d_in[0];
    const float* wpack  = (const float*)d_in[1];
    const float* wo     = (const float*)d_in[2];
    float* out = (float*)d_out;

    __half *qkvh, *qkvl, *h16, *wp16, *wo16, *at16;
    cudaGetSymbolAddress((void**)&qkvh, g_qkvh);
    cudaGetSymbolAddress((void**)&qkvl, g_qkvl);
    cudaGetSymbolAddress((void**)&h16,  g_h16);
    cudaGetSymbolAddress((void**)&wp16, g_wp16);
    cudaGetSymbolAddress((void**)&wo16, g_wo16);
    cudaGetSymbolAddress((void**)&at16, g_attno16);

    cudaFuncSetAttribute((const void*)gemm16p<true>,
                         cudaFuncAttributeMaxDynamicSharedMemorySize, GEMM_SMEM_SINGLE);
    cudaFuncSetAttribute((const void*)gemm16p<false>,
                         cudaFuncAttributeMaxDynamicSharedMemorySize, GEMM_SMEM_SINGLE);
    cudaFuncSetAttribute((const void*)flash16_kernel,
                         cudaFuncAttributeMaxDynamicSharedMemorySize, FSMEM);

    // 0. pre-conversions: H, Wpack (full), Wo -> plain fp16
    cvt_fused3_kernel<<<8192, 256>>>(
        (const float4*)hidden, (uint2*)h16, (int)((size_t)S_LEN * HID / 4),
        (const float4*)wpack, (uint2*)wp16, (int)((size_t)QKV_N * HID / 4),
        (const float4*)wo, (uint2*)wo16, (int)((size_t)HID * HID / 4));

    // 1. QKV projection (plain fp16 B; split-out hi/lo for Q,K)
    dim3 g1(S_LEN / MT, QKV_N / NT);
    gemm16p<true><<<g1, 256, GEMM_SMEM_SINGLE>>>(
        h16, wp16, nullptr, qkvh, qkvl, S_LEN, QKV_N, HID);

    // 2. Causal flash attention (BQ=128, triple-buffered K/V) -> fp16
    dim3 g2(NH, S_LEN / BQ);
    flash16_kernel<<<g2, 256, FSMEM>>>(qkvh, qkvl, at16);

    // 3. Output projection (plain fp16) -> fp32 out
    dim3 g3(S_LEN / MT, HID / NT);
    gemm16p<false><<<g3, 256, GEMM_SMEM_SINGLE>>>(
        at16, wo16, out, nullptr, nullptr, S_LEN, HID, HID);
}

// round 13
// speedup vs baseline: 2.0817x; 1.0299x over previous
#include <cuda_runtime.h>
#include <cuda_fp16.h>
#include <cstdint>
#include <math.h>

#define S_LEN 2048
#define HID   5120
#define NH    40
#define HD    128
#define QKV_N (3*HID)   // 15360

// ---- fp16 mma GEMM tiling: KT=64, padded rows (16B-period pad) ----
#define MT 128
#define NT 128
#define KT 64
#define BSTR 72                         // halves per smem row (64 data + 8 pad)
#define TILE_BYTES (128*BSTR*2)         // 18432 per operand tile
#define STAGE_BYTES (2*TILE_BYTES)      // A + B = 36864
#define STAGES 3
#define GEMM_SMEM (STAGES*STAGE_BYTES)  // 110592 (x2 CTA = 221184)

// ---- flash-attention (fp16 tensor, BQ=128, triple-buffered K/V) ----
#define BQ 128
#define BKV 64
#define AQS 136                          // halves stride for 128-wide rows
#define KV_TILE (BKV*AQS*2)              // 17408
#define Q_TILE  (BQ*AQS*2)               // 34816
#define KVBUF   (3*KV_TILE)              // Kh,Kl,Vh = 52224
#define KV_STAGES 3
#define FSMEM   (2*Q_TILE + KV_STAGES*KVBUF)   // 226304

// Scratch (allocation-free rule: __device__ globals)
__device__ __half g_qkvh[(size_t)S_LEN * QKV_N];       // QKV hi fp16
__device__ __half g_qkvl[(size_t)S_LEN * QKV_N];       // QKV lo fp16 (Q,K only)
__device__ __half g_h16[(size_t)S_LEN * HID];          // hidden fp16
__device__ __half g_wp16[(size_t)QKV_N * HID];         // Wpack fp16 (plain)
__device__ __half g_wo16[(size_t)HID * HID];           // Wo fp16
__device__ __half g_attno16[(size_t)S_LEN * HID];      // attention out fp16

// ============================================================================
// PTX helpers
// ============================================================================
__device__ __forceinline__ uint32_t smem_u32(const void* p) {
    uint32_t a;
    asm("{ .reg .u64 t; cvta.to.shared.u64 t, %1; cvt.u32.u64 %0, t; }"
        : "=r"(a) : "l"(p));
    return a;
}

__device__ __forceinline__ void ldsm4(uint32_t* r, uint32_t a) {
    asm volatile("ldmatrix.sync.aligned.m8n8.x4.shared.b16 {%0,%1,%2,%3}, [%4];"
                 : "=r"(r[0]), "=r"(r[1]), "=r"(r[2]), "=r"(r[3]) : "r"(a));
}
__device__ __forceinline__ void ldsm4t(uint32_t* r, uint32_t a) {
    asm volatile("ldmatrix.sync.aligned.m8n8.x4.trans.shared.b16 {%0,%1,%2,%3}, [%4];"
                 : "=r"(r[0]), "=r"(r[1]), "=r"(r[2]), "=r"(r[3]) : "r"(a));
}

__device__ __forceinline__ void mma16(float* c, const uint32_t* a,
                                      uint32_t b0, uint32_t b1) {
    asm volatile(
        "mma.sync.aligned.m16n8k16.row.col.f32.f16.f16.f32 "
        "{%0,%1,%2,%3}, {%4,%5,%6,%7}, {%8,%9}, {%0,%1,%2,%3};"
        : "+f"(c[0]), "+f"(c[1]), "+f"(c[2]), "+f"(c[3])
        : "r"(a[0]), "r"(a[1]), "r"(a[2]), "r"(a[3]), "r"(b0), "r"(b1));
}

__device__ __forceinline__ uint32_t packh2(float a, float b) {
    __half2 h = __floats2half2_rn(a, b);
    return *reinterpret_cast<uint32_t*>(&h);
}

__device__ __forceinline__ uint2 cvt4(const float4 v) {
    uint2 r; r.x = packh2(v.x, v.y); r.y = packh2(v.z, v.w); return r;
}

__device__ __forceinline__ void cpa16(uint32_t dst, const void* src) {
    asm volatile("cp.async.cg.shared.global [%0], [%1], 16;"
                 :: "r"(dst), "l"(src) : "memory");
}
__device__ __forceinline__ void cp_commit() {
    asm volatile("cp.async.commit_group;" ::: "memory");
}
template<int N> __device__ __forceinline__ void cp_wait() {
    asm volatile("cp.async.wait_group %0;" :: "n"(N) : "memory");
}

// ============================================================================
// Pre-conversion: fused plain conversions (hidden, Wpack full, Wo)
// ============================================================================
__global__ void cvt_fused3_kernel(const float4* __restrict__ a, uint2* __restrict__ ao, int na,
                                  const float4* __restrict__ b, uint2* __restrict__ bo, int nb,
                                  const float4* __restrict__ c, uint2* __restrict__ co, int nc) {
    const int tot = na + nb + nc;
    for (int i = blockIdx.x * blockDim.x + threadIdx.x; i < tot;
         i += gridDim.x * blockDim.x) {
        if (i < na) ao[i] = cvt4(a[i]);
        else if (i < na + nb) bo[i - na] = cvt4(b[i - na]);
        else co[i - na - nb] = cvt4(c[i - na - nb]);
    }
}

// ============================================================================
// fp16 tensor GEMM (TN), plain B, KT=64, 3-stage cp.async pipeline, 2 CTAs/SM.
// SPLITOUT: write hi/lo fp16 split of the fp32 accumulator (lo for n0<2*HID,
//           i.e. Q and K outputs; V gets hi only).
// ============================================================================
template<bool SPLITOUT>
__global__ __launch_bounds__(256, 2)
void gemm16p(const __half* __restrict__ A, const __half* __restrict__ Bh,
             float* __restrict__ Cf,
             __half* __restrict__ Chi, __half* __restrict__ Clo,
             int M, int N, int K) {
    extern __shared__ __align__(16) char sm[];
    const uint32_t sb = smem_u32(sm);

    const int t   = threadIdx.x;
    const int wid = t >> 5;
    const int ln  = t & 31;
    const int m0  = blockIdx.x * MT;
    const int n0  = blockIdx.y * NT;
    const int wm  = (wid >> 1) * 32;
    const int wn  = (wid & 1) * 64;

    // cp.async geometry: row r0 (0..31) + 32i, chunk sg (0..7, 16B each)
    const int r0 = t >> 3;
    const int sg = t & 7;
    const __half* Ag = A  + (size_t)(m0 + r0) * K + sg * 8;
    const __half* Bg = Bh + (size_t)(n0 + r0) * K + sg * 8;
    uint32_t dA[4];
#pragma unroll
    for (int i = 0; i < 4; i++)
        dA[i] = (uint32_t)(r0 + 32 * i) * (BSTR * 2) + sg * 16;

    const uint32_t aoff = ((uint32_t)(wm + (ln & 15)) * BSTR + 8u * (ln >> 4)) * 2;
    const uint32_t boff = TILE_BYTES +
        ((uint32_t)(wn + (ln & 7) + 8 * (ln >> 4)) * BSTR + 8u * ((ln >> 3) & 1)) * 2;

    float acc[2][8][4];
#pragma unroll
    for (int mi = 0; mi < 2; mi++)
#pragma unroll
        for (int nf = 0; nf < 8; nf++)
#pragma unroll
            for (int r = 0; r < 4; r++) acc[mi][nf][r] = 0.0f;

    const int NKT = K / KT;   // 80

    auto issue = [&](int st, int kt) {
        const uint32_t base = sb + (uint32_t)st * STAGE_BYTES;
        const size_t ko = (size_t)kt * KT;
#pragma unroll
        for (int i = 0; i < 4; i++) {
            cpa16(base + dA[i], Ag + (size_t)(32 * i) * K + ko);
            cpa16(base + TILE_BYTES + dA[i], Bg + (size_t)(32 * i) * K + ko);
        }
    };

#pragma unroll
    for (int s = 0; s < STAGES - 1; s++) { issue(s, s); cp_commit(); }

#pragma unroll 1
    for (int kt = 0; kt < NKT; kt++) {
        cp_wait<STAGES - 2>();
        __syncthreads();

        const uint32_t so = sb + (uint32_t)(kt % STAGES) * STAGE_BYTES;
#pragma unroll
        for (int ks = 0; ks < 4; ks++) {
            const uint32_t ko = ks * 32;   // 16 halves
            uint32_t af[2][4];
            ldsm4(af[0], so + aoff + ko);
            ldsm4(af[1], so + aoff + 16 * BSTR * 2 + ko);
            uint32_t bh[4][4];
#pragma unroll
            for (int p = 0; p < 4; p++)
                ldsm4(bh[p], so + boff + p * (16 * BSTR * 2) + ko);
#pragma unroll
            for (int mi = 0; mi < 2; mi++)
#pragma unroll
                for (int nf = 0; nf < 8; nf++)
                    mma16(acc[mi][nf], af[mi],
                          bh[nf >> 1][(nf & 1) * 2], bh[nf >> 1][(nf & 1) * 2 + 1]);
        }

        const int nk = kt + STAGES - 1;
        if (nk < NKT) issue(nk % STAGES, nk);
        cp_commit();
    }

    // epilogue
    const bool writeLo = SPLITOUT && (n0 < 2 * HID);   // Q,K get hi/lo outputs
#pragma unroll
    for (int mi = 0; mi < 2; mi++) {
        const int r = m0 + wm + mi * 16 + (ln >> 2);
#pragma unroll
        for (int nf = 0; nf < 8; nf++) {
            const int cc = n0 + wn + nf * 8 + (ln & 3) * 2;
            if (SPLITOUT) {
#pragma unroll
                for (int hh = 0; hh < 2; hh++) {
                    const float v0 = acc[mi][nf][2 * hh], v1 = acc[mi][nf][2 * hh + 1];
                    const __half h0 = __float2half_rn(v0), h1 = __float2half_rn(v1);
                    const size_t off = (size_t)(r + 8 * hh) * N + cc;
                    *(uint32_t*)(Chi + off) = packh2(v0, v1);
                    if (writeLo)
                        *(uint32_t*)(Clo + off) =
                            packh2(v0 - __half2float(h0), v1 - __half2float(h1));
                }
            } else {
                *(float2*)(Cf + (size_t)r * N + cc) =
                    make_float2(acc[mi][nf][0], acc[mi][nf][1]);
                *(float2*)(Cf + (size_t)(r + 8) * N + cc) =
                    make_float2(acc[mi][nf][2], acc[mi][nf][3]);
            }
        }
    }
}

// ============================================================================
// Flash attention (unchanged), fp16 tensor, causal. BQ=128, 256 thr,
// triple-buffered K/V via cp.async; one sync per KV block; Q in registers.
// S = QhKh + QhKl + QlKh; O += P*Vh. Grid (NH, S/BQ) with qb reversed.
// ============================================================================
__global__ __launch_bounds__(256, 1)
void flash16_kernel(const __half* __restrict__ qh, const __half* __restrict__ ql,
                    __half* __restrict__ out) {
    extern __shared__ __align__(16) char sm[];
    const uint32_t sb = smem_u32(sm);
    const uint32_t uQh = sb;
    const uint32_t uQl = sb + Q_TILE;
    const uint32_t uBuf0 = sb + 2 * Q_TILE;

    const int head = blockIdx.x;
    const int qb   = (int)gridDim.y - 1 - (int)blockIdx.y;   // heavy first
    const int q0   = qb * BQ;
    const int t    = threadIdx.x;
    const int w    = t >> 5;
    const int ln   = t & 31;
    const int m0w  = w * 16;
    const float scale = 0.08838834764831845f;   // 1/sqrt(128)

    const int lr  = t >> 2;            // 0..63
    const int lc  = (t & 3) * 4;       // chunk base 0,4,8,12

    auto issueKV = [&](int kb) {
        const uint32_t base = uBuf0 + (uint32_t)(kb % KV_STAGES) * KVBUF;
        const size_t gk = (size_t)(kb * BKV + lr) * QKV_N + HID + head * HD;
        const size_t gv = gk + HID;
        const uint32_t ro = (uint32_t)lr * (AQS * 2);
#pragma unroll
        for (int i = 0; i < 4; i++) {
            const int c = lc + i;
            cpa16(base + ro + c * 16, qh + gk + c * 8);                    // Kh
            cpa16(base + KV_TILE + ro + c * 16, ql + gk + c * 8);          // Kl
            cpa16(base + 2 * KV_TILE + ro + c * 16, qh + gv + c * 8);      // Vh
        }
    };

    // ---- prologue: Q + KV0 as one group, KV1 as second ----
#pragma unroll
    for (int pass = 0; pass < 2; pass++) {
        const int r = pass * 64 + lr;
        const size_t go = (size_t)(q0 + r) * QKV_N + head * HD;
        const uint32_t ro = (uint32_t)r * (AQS * 2);
#pragma unroll
        for (int i = 0; i < 4; i++) {
            const int c = lc + i;
            cpa16(uQh + ro + c * 16, qh + go + c * 8);
            cpa16(uQl + ro + c * 16, ql + go + c * 8);
        }
    }
    issueKV(0);
    cp_commit();          // group: Q + KV0
    issueKV(1);
    cp_commit();          // group: KV1

    const int nkb = 2 * (qb + 1);

    cp_wait<1>();         // Q + KV0 ready
    __syncthreads();

    // ---- hoist Q fragments (hi/lo) to registers ----
    const uint32_t aQ = ((uint32_t)(m0w + (ln & 15)) * AQS + 8u * (ln >> 4)) * 2;
    uint32_t qhf[8][4], qlf[8][4];
#pragma unroll
    for (int ks = 0; ks < 8; ks++) {
        ldsm4(qhf[ks], uQh + aQ + ks * 32);
        ldsm4(qlf[ks], uQl + aQ + ks * 32);
    }

    float m_i[2] = {-1e30f, -1e30f};
    float l_i[2] = {0.0f, 0.0f};
    float o[16][4];
#pragma unroll
    for (int d = 0; d < 16; d++)
#pragma unroll
        for (int r = 0; r < 4; r++) o[d][r] = 0.0f;

    const uint32_t bK = ((uint32_t)((ln & 7) + 8 * (ln >> 4)) * AQS + 8u * ((ln >> 3) & 1)) * 2;
    const uint32_t bV = ((uint32_t)((ln & 7) + 8 * ((ln >> 3) & 1)) * AQS + 8u * (ln >> 4)) * 2;

    const int r1g = q0 + m0w + (ln >> 2);
    const int r2g = r1g + 8;

#pragma unroll 1
    for (int kb = 0; kb < nkb; kb++) {
        const int k0 = kb * BKV;

        if (kb + 2 < nkb) issueKV(kb + 2);
        cp_commit();

        if (k0 <= q0 + m0w + 15) {
            const uint32_t cKh = uBuf0 + (uint32_t)(kb % KV_STAGES) * KVBUF;
            const uint32_t cKl = cKh + KV_TILE;
            const uint32_t cVh = cKh + 2 * KV_TILE;

            float s[8][4];
#pragma unroll
            for (int nf = 0; nf < 8; nf++)
#pragma unroll
                for (int r = 0; r < 4; r++) s[nf][r] = 0.0f;

#pragma unroll
            for (int ks = 0; ks < 8; ks++) {
                const uint32_t ko = ks * 32;
                uint32_t kh[4][4], kl[4][4];
#pragma unroll
                for (int p = 0; p < 4; p++) {
                    ldsm4(kh[p], cKh + bK + p * (16 * AQS * 2) + ko);
                    ldsm4(kl[p], cKl + bK + p * (16 * AQS * 2) + ko);
                }
#pragma unroll
                for (int nf = 0; nf < 8; nf++) {
                    const uint32_t h0 = kh[nf >> 1][(nf & 1) * 2];
                    const uint32_t h1 = kh[nf >> 1][(nf & 1) * 2 + 1];
                    const uint32_t l0 = kl[nf >> 1][(nf & 1) * 2];
                    const uint32_t l1 = kl[nf >> 1][(nf & 1) * 2 + 1];
                    mma16(s[nf], qhf[ks], h0, h1);
                    mma16(s[nf], qhf[ks], l0, l1);
                    mma16(s[nf], qlf[ks], h0, h1);
                }
            }

            const bool needMask = (k0 + BKV - 1 > q0 + m0w);
            float mx1 = -1e30f, mx2 = -1e30f;
#pragma unroll
            for (int nf = 0; nf < 8; nf++) {
                float v0 = s[nf][0] * scale, v1 = s[nf][1] * scale;
                float v2 = s[nf][2] * scale, v3 = s[nf][3] * scale;
                if (needMask) {
                    const int cb = k0 + nf * 8 + 2 * (ln & 3);
                    if (cb     > r1g) v0 = -1e30f;
                    if (cb + 1 > r1g) v1 = -1e30f;
                    if (cb     > r2g) v2 = -1e30f;
                    if (cb + 1 > r2g) v3 = -1e30f;
                }
                s[nf][0] = v0; s[nf][1] = v1; s[nf][2] = v2; s[nf][3] = v3;
                mx1 = fmaxf(mx1, fmaxf(v0, v1));
                mx2 = fmaxf(mx2, fmaxf(v2, v3));
            }
            mx1 = fmaxf(mx1, __shfl_xor_sync(0xffffffffu, mx1, 1));
            mx1 = fmaxf(mx1, __shfl_xor_sync(0xffffffffu, mx1, 2));
            mx2 = fmaxf(mx2, __shfl_xor_sync(0xffffffffu, mx2, 1));
            mx2 = fmaxf(mx2, __shfl_xor_sync(0xffffffffu, mx2, 2));

            const float mn1 = fmaxf(m_i[0], mx1);
            const float mn2 = fmaxf(m_i[1], mx2);
            const float corr1 = __expf(m_i[0] - mn1);
            const float corr2 = __expf(m_i[1] - mn2);
            m_i[0] = mn1; m_i[1] = mn2;

            float rs1 = 0.0f, rs2 = 0.0f;
#pragma unroll
            for (int nf = 0; nf < 8; nf++) {
                float p0 = __expf(s[nf][0] - mn1);
                float p1 = __expf(s[nf][1] - mn1);
                float p2 = __expf(s[nf][2] - mn2);
                float p3 = __expf(s[nf][3] - mn2);
                rs1 += p0 + p1; rs2 += p2 + p3;
                s[nf][0] = p0; s[nf][1] = p1; s[nf][2] = p2; s[nf][3] = p3;
            }
            rs1 += __shfl_xor_sync(0xffffffffu, rs1, 1);
            rs1 += __shfl_xor_sync(0xffffffffu, rs1, 2);
            rs2 += __shfl_xor_sync(0xffffffffu, rs2, 1);
            rs2 += __shfl_xor_sync(0xffffffffu, rs2, 2);
            l_i[0] = l_i[0] * corr1 + rs1;
            l_i[1] = l_i[1] * corr2 + rs2;

#pragma unroll
            for (int d = 0; d < 16; d++) {
                o[d][0] *= corr1; o[d][1] *= corr1;
                o[d][2] *= corr2; o[d][3] *= corr2;
            }

            uint32_t pa[4][4];
#pragma unroll
            for (int tk = 0; tk < 4; tk++) {
                pa[tk][0] = packh2(s[2 * tk][0],     s[2 * tk][1]);
                pa[tk][1] = packh2(s[2 * tk][2],     s[2 * tk][3]);
                pa[tk][2] = packh2(s[2 * tk + 1][0], s[2 * tk + 1][1]);
                pa[tk][3] = packh2(s[2 * tk + 1][2], s[2 * tk + 1][3]);
            }

#pragma unroll
            for (int tk = 0; tk < 4; tk++) {
                const uint32_t rowo = (uint32_t)(16 * tk) * AQS * 2;
#pragma unroll
                for (int p = 0; p < 8; p++) {
                    uint32_t vh[4];
                    ldsm4t(vh, cVh + rowo + bV + (uint32_t)p * 32);
                    mma16(o[2 * p],     pa[tk], vh[0], vh[1]);
                    mma16(o[2 * p + 1], pa[tk], vh[2], vh[3]);
                }
            }
        }

        if (kb + 1 < nkb) {
            cp_wait<1>();      // next block's K/V landed
            __syncthreads();   // single barrier per iteration
        }
    }

    // ---- epilogue: fp16 output ----
    const float inv1 = 1.0f / l_i[0];
    const float inv2 = 1.0f / l_i[1];
#pragma unroll
    for (int d = 0; d < 16; d++) {
        const int cc = head * HD + d * 8 + 2 * (ln & 3);
        *(__half2*)(out + (size_t)r1g * HID + cc) =
            __floats2half2_rn(o[d][0] * inv1, o[d][1] * inv1);
        *(__half2*)(out + (size_t)r2g * HID + cc) =
            __floats2half2_rn(o[d][2] * inv2, o[d][3] * inv2);
    }
}

// ============================================================================
// Launch
// ============================================================================
extern "C" void kernel_launch(void* const* d_in, const int* in_sizes, int n_in,
                              void* d_out, int out_size) {
    const float* hidden = (const float*)d_in[0];
    const float* wpack  = (const float*)d_in[1];
    const float* wo     = (const float*)d_in[2];
    float* out = (float*)d_out;

    __half *qkvh, *qkvl, *h16, *wp16, *wo16, *at16;
    cudaGetSymbolAddress((void**)&qkvh, g_qkvh);
    cudaGetSymbolAddress((void**)&qkvl, g_qkvl);
    cudaGetSymbolAddress((void**)&h16,  g_h16);
    cudaGetSymbolAddress((void**)&wp16, g_wp16);
    cudaGetSymbolAddress((void**)&wo16, g_wo16);
    cudaGetSymbolAddress((void**)&at16, g_attno16);

    cudaFuncSetAttribute((const void*)gemm16p<true>,
                         cudaFuncAttributeMaxDynamicSharedMemorySize, GEMM_SMEM);
    cudaFuncSetAttribute((const void*)gemm16p<false>,
                         cudaFuncAttributeMaxDynamicSharedMemorySize, GEMM_SMEM);
    cudaFuncSetAttribute((const void*)flash16_kernel,
                         cudaFuncAttributeMaxDynamicSharedMemorySize, FSMEM);

    // 0. pre-conversions: H, Wpack (full), Wo -> plain fp16
    cvt_fused3_kernel<<<8192, 256>>>(
        (const float4*)hidden, (uint2*)h16, (int)((size_t)S_LEN * HID / 4),
        (const float4*)wpack, (uint2*)wp16, (int)((size_t)QKV_N * HID / 4),
        (const float4*)wo, (uint2*)wo16, (int)((size_t)HID * HID / 4));

    // 1. QKV projection (plain fp16 B; split-out hi/lo for Q,K)
    dim3 g1(S_LEN / MT, QKV_N / NT);
    gemm16p<true><<<g1, 256, GEMM_SMEM>>>(
        h16, wp16, nullptr, qkvh, qkvl, S_LEN, QKV_N, HID);

    // 2. Causal flash attention (BQ=128, triple-buffered K/V) -> fp16
    dim3 g2(NH, S_LEN / BQ);
    flash16_kernel<<<g2, 256, FSMEM>>>(qkvh, qkvl, at16);

    // 3. Output projection (plain fp16) -> fp32 out
    dim3 g3(S_LEN / MT, HID / NT);
    gemm16p<false><<<g3, 256, GEMM_SMEM>>>(
        at16, wo16, out, nullptr, nullptr, S_LEN, HID, HID);
}